// round 13
// baseline (speedup 1.0000x reference)
#include <cuda_runtime.h>
#include <cuda_fp16.h>
#include <cstdint>

// DiffUnpool: out[b] = S[b] @ x[b]
//   S: [16, 2048, 256] f32   x: [16, 256, 256] f32   out: [16, 2048, 256] f32
// R13 = R12 (fp16 m16n8k16, pre-converted x, cp.async B, register-staged A)
// with 8 warps of 64x32 (CTA 128x128, 256 threads): acc 64/thread -> occ 2
// -> 4 warps/SMSP for latency hiding. Arithmetic identical to R12.

#define A_BUF 8192                    // 128 rows x 64B fp16
#define B_BUF 8192                    // 32 rows x 256B fp16
#define OFF_B (2 * A_BUF)             // 16384
#define SM_BYTES (2 * A_BUF + 2 * B_BUF)   // 32768

__device__ __align__(16) __half g_X16[16 * 256 * 256];   // 2 MB scratch

__global__ void convert_x(const float* __restrict__ X) {
    int i = blockIdx.x * blockDim.x + threadIdx.x;        // 0..131071
    const float4* src = (const float4*)X;
    float4 v0 = src[2 * i], v1 = src[2 * i + 1];
    __half2 h0 = __floats2half2_rn(v0.x, v0.y);
    __half2 h1 = __floats2half2_rn(v0.z, v0.w);
    __half2 h2 = __floats2half2_rn(v1.x, v1.y);
    __half2 h3 = __floats2half2_rn(v1.z, v1.w);
    uint4 u = make_uint4(*(uint32_t*)&h0, *(uint32_t*)&h1,
                         *(uint32_t*)&h2, *(uint32_t*)&h3);
    ((uint4*)g_X16)[i] = u;
}

static __device__ __forceinline__ uint32_t cvta_smem(const void* p) {
    uint32_t a;
    asm("{ .reg .u64 t; cvta.to.shared.u64 t, %1; cvt.u32.u64 %0, t; }"
        : "=r"(a) : "l"(p));
    return a;
}
static __device__ __forceinline__ uint32_t h2u(float x, float y) {
    __half2 h = __floats2half2_rn(x, y);
    return *(uint32_t*)&h;
}
static __device__ __forceinline__ uint4 cvt8(float4 a, float4 b) {
    return make_uint4(h2u(a.x, a.y), h2u(a.z, a.w), h2u(b.x, b.y), h2u(b.z, b.w));
}

#define CP16(dst, src) \
    asm volatile("cp.async.cg.shared.global [%0], [%1], 16;" :: "r"(dst), "l"(src))
#define CPCOMMIT() asm volatile("cp.async.commit_group;" ::: "memory")
#define CPWAIT1()  asm volatile("cp.async.wait_group 1;" ::: "memory")

#define LDSM4(r0, r1, r2, r3, a) \
    asm volatile("ldmatrix.sync.aligned.m8n8.x4.shared.b16 {%0,%1,%2,%3}, [%4];" \
                 : "=r"(r0), "=r"(r1), "=r"(r2), "=r"(r3) : "r"(a))
#define LDSM4T(r0, r1, r2, r3, a) \
    asm volatile("ldmatrix.sync.aligned.m8n8.x4.trans.shared.b16 {%0,%1,%2,%3}, [%4];" \
                 : "=r"(r0), "=r"(r1), "=r"(r2), "=r"(r3) : "r"(a))
#define MMAF16(d, a, b0, b1) \
    asm volatile("mma.sync.aligned.m16n8k16.row.col.f32.f16.f16.f32 " \
                 "{%0,%1,%2,%3},{%4,%5,%6,%7},{%8,%9},{%0,%1,%2,%3};" \
                 : "+f"((d)[0]), "+f"((d)[1]), "+f"((d)[2]), "+f"((d)[3]) \
                 : "r"((a)[0]), "r"((a)[1]), "r"((a)[2]), "r"((a)[3]), "r"(b0), "r"(b1))

__global__ __launch_bounds__(256, 2)
void diffunpool_f16_v3(const float* __restrict__ S, float* __restrict__ O) {
    __shared__ __align__(16) char smbuf[SM_BYTES];

    const int nt = blockIdx.x;   // 0..1
    const int mt = blockIdx.y;   // 0..15
    const int b  = blockIdx.z;   // 0..15

    const float*  Sb  = S + ((size_t)b * 2048 + (size_t)mt * 128) * 256;
    const __half* Xb  = g_X16 + (size_t)b * 65536 + (size_t)nt * 128;
    float*        Ob  = O + ((size_t)b * 2048 + (size_t)mt * 128) * 256 + (size_t)nt * 128;

    const int tid = threadIdx.x, wid = tid >> 5, lane = tid & 31;
    const int wm = (wid & 1) * 64;       // 2 m-groups of 64
    const int wn = (wid >> 1) * 32;      // 4 n-groups of 32
    const uint32_t sb = cvta_smem(smbuf);

    // ---- A staging: 512 pieces (128 rows x 4 segs of 8 fp32), 2 per thread
    const int a_m = tid >> 2, a_seg = tid & 3;          // rows 0..63 (+64 for q=1)
    const float*   pA   = Sb + (size_t)a_m * 256 + a_seg * 8;
    const uint32_t aSts = (uint32_t)a_m * 64
                        + (uint32_t)((a_seg ^ ((a_m >> 1) & 3)) << 4);
    // q=1: rows +64 -> +16384 floats in gmem, +4096 bytes in smem (same swizzle key:
    // (a_m>>1)&3 uses row bits 1-2, unchanged by +64).

    // ---- B cp.async: 512 pieces (32 rows x 16 segs), 2 per thread
    auto issueB = [&](int c, int bf) {
        const uint32_t bbuf = sb + OFF_B + (uint32_t)bf * B_BUF;
#pragma unroll
        for (int q = 0; q < 2; q++) {
            int flat = q * 256 + tid;
            int k = flat >> 4, s = flat & 15;
            const __half* src = Xb + (size_t)(c * 32 + k) * 256 + s * 8;
            uint32_t dst = bbuf + (uint32_t)k * 256 + (uint32_t)((s ^ (k & 7)) << 4);
            CP16(dst, src);
        }
        CPCOMMIT();
    };

    // ---- fragment addressing (layouts R11/R12-proven)
    const int m_low = (lane & 7) + 8 * ((lane >> 3) & 1);
    const int halfk = lane >> 4;
    uint32_t rowA[4], swzA[4];
#pragma unroll
    for (int mf = 0; mf < 4; mf++) {
        int row = wm + mf * 16 + m_low;
        rowA[mf] = (uint32_t)row * 64;
        swzA[mf] = (uint32_t)((row >> 1) & 3);
    }
    const int b_kl  = lane & 15;
    const int kswz  = b_kl & 7;
    const int b_c0  = (wn >> 3) + (lane >> 4);          // 0..13
    const uint32_t bRow = (uint32_t)b_kl * 256;

    float d[4][4][4];                                    // 64 accumulators
#pragma unroll
    for (int mf = 0; mf < 4; mf++)
#pragma unroll
        for (int j = 0; j < 4; j++)
#pragma unroll
            for (int r = 0; r < 4; r++) d[mf][j][r] = 0.0f;

    // ---- prologue
    float4 va[4];
#pragma unroll
    for (int q = 0; q < 2; q++) {
        va[2*q]   = *(const float4*)(pA + (size_t)q * 16384);
        va[2*q+1] = *(const float4*)(pA + (size_t)q * 16384 + 4);
    }
    issueB(0, 0);
    issueB(1, 1);

    for (int c = 0; c < 8; c++) {
        const uint32_t aOff = (uint32_t)(c & 1) * A_BUF;
        const uint32_t bOff = (uint32_t)(c & 1) * B_BUF;

        // ---- convert + store A chunk c
#pragma unroll
        for (int q = 0; q < 2; q++)
            *(uint4*)(smbuf + aOff + aSts + q * 4096) = cvt8(va[2*q], va[2*q+1]);

        CPWAIT1();
        __syncthreads();

        // ---- prefetch A chunk c+1
        if (c < 7) {
            const float* nA = pA + (c + 1) * 32;
#pragma unroll
            for (int q = 0; q < 2; q++) {
                va[2*q]   = *(const float4*)(nA + (size_t)q * 16384);
                va[2*q+1] = *(const float4*)(nA + (size_t)q * 16384 + 4);
            }
        }

        // ---- compute chunk c: 2 k16 steps
#pragma unroll
        for (int ks = 0; ks < 2; ks++) {
            uint32_t a[4][4];
#pragma unroll
            for (int mf = 0; mf < 4; mf++) {
                uint32_t seg  = (uint32_t)(2 * ks + halfk);
                uint32_t addr = sb + aOff + rowA[mf] + ((seg ^ swzA[mf]) << 4);
                LDSM4(a[mf][0], a[mf][1], a[mf][2], a[mf][3], addr);
            }
            uint32_t bb[2][4];
            const uint32_t bkoff = sb + OFF_B + bOff + (uint32_t)(ks * 4096) + bRow;
#pragma unroll
            for (int nb = 0; nb < 2; nb++) {
                uint32_t chunk = (uint32_t)((b_c0 + nb * 2) ^ kswz);
                LDSM4T(bb[nb][0], bb[nb][1], bb[nb][2], bb[nb][3], bkoff + (chunk << 4));
            }
#pragma unroll
            for (int mf = 0; mf < 4; mf++)
#pragma unroll
                for (int nb = 0; nb < 2; nb++) {
                    MMAF16(d[mf][2*nb],   a[mf], bb[nb][0], bb[nb][1]);
                    MMAF16(d[mf][2*nb+1], a[mf], bb[nb][2], bb[nb][3]);
                }
        }
        __syncthreads();
        if (c < 6) issueB(c + 2, c & 1);
    }

    // ---- epilogue
    const int group = lane >> 2;
    const int tcol  = (lane & 3) * 2;
#pragma unroll
    for (int mf = 0; mf < 4; mf++) {
        int m0 = wm + mf * 16 + group;
#pragma unroll
        for (int j = 0; j < 4; j++) {
            int n0 = wn + j * 8 + tcol;
            *(float2*)(Ob + (size_t)m0 * 256 + n0)       = make_float2(d[mf][j][0], d[mf][j][1]);
            *(float2*)(Ob + (size_t)(m0 + 8) * 256 + n0) = make_float2(d[mf][j][2], d[mf][j][3]);
        }
    }
}

extern "C" void kernel_launch(void* const* d_in, const int* in_sizes, int n_in,
                              void* d_out, int out_size) {
    const float* S = nullptr;
    const float* X = nullptr;
    for (int i = 0; i < n_in; i++) {
        if (in_sizes[i] == 8388608)      S = (const float*)d_in[i];
        else if (in_sizes[i] == 1048576) X = (const float*)d_in[i];
    }
    float* O = (float*)d_out;

    convert_x<<<512, 256>>>(X);
    dim3 grid(2, 16, 16);
    diffunpool_f16_v3<<<grid, 256>>>(S, O);
}

// round 14
// speedup vs baseline: 1.0694x; 1.0694x over previous
#include <cuda_runtime.h>
#include <cuda_fp16.h>
#include <cstdint>

// DiffUnpool: out[b] = S[b] @ x[b]
//   S: [16, 2048, 256] f32   x: [16, 256, 256] f32   out: [16, 2048, 256] f32
// R14 = R12 (fp16 m16n8k16, CTA 128x128, 4 warps 64x64, pre-converted x,
// cp.async B, register-staged A) with ONE barrier per K-chunk:
//   B ring of 4 buffers, A ring of 2 buffers, exact cp.async group accounting
//   (empty commit_groups in the tail). Arithmetic identical to R12.

#define A_BUF 8192                    // 128 rows x 64B fp16
#define B_BUF 8192                    // 32 rows x 256B fp16
#define OFF_B (2 * A_BUF)             // 16384
#define SM_BYTES (2 * A_BUF + 4 * B_BUF)   // 49152 (= 48KB static limit)

__device__ __align__(16) __half g_X16[16 * 256 * 256];   // 2 MB scratch

__global__ void convert_x(const float* __restrict__ X) {
    int i = blockIdx.x * blockDim.x + threadIdx.x;        // 0..131071
    const float4* src = (const float4*)X;
    float4 v0 = src[2 * i], v1 = src[2 * i + 1];
    __half2 h0 = __floats2half2_rn(v0.x, v0.y);
    __half2 h1 = __floats2half2_rn(v0.z, v0.w);
    __half2 h2 = __floats2half2_rn(v1.x, v1.y);
    __half2 h3 = __floats2half2_rn(v1.z, v1.w);
    uint4 u = make_uint4(*(uint32_t*)&h0, *(uint32_t*)&h1,
                         *(uint32_t*)&h2, *(uint32_t*)&h3);
    ((uint4*)g_X16)[i] = u;
}

static __device__ __forceinline__ uint32_t cvta_smem(const void* p) {
    uint32_t a;
    asm("{ .reg .u64 t; cvta.to.shared.u64 t, %1; cvt.u32.u64 %0, t; }"
        : "=r"(a) : "l"(p));
    return a;
}
static __device__ __forceinline__ uint32_t h2u(float x, float y) {
    __half2 h = __floats2half2_rn(x, y);
    return *(uint32_t*)&h;
}
static __device__ __forceinline__ uint4 cvt8(float4 a, float4 b) {
    return make_uint4(h2u(a.x, a.y), h2u(a.z, a.w), h2u(b.x, b.y), h2u(b.z, b.w));
}

#define CP16(dst, src) \
    asm volatile("cp.async.cg.shared.global [%0], [%1], 16;" :: "r"(dst), "l"(src))
#define CPCOMMIT() asm volatile("cp.async.commit_group;" ::: "memory")
#define CPWAIT2()  asm volatile("cp.async.wait_group 2;" ::: "memory")

#define LDSM4(r0, r1, r2, r3, a) \
    asm volatile("ldmatrix.sync.aligned.m8n8.x4.shared.b16 {%0,%1,%2,%3}, [%4];" \
                 : "=r"(r0), "=r"(r1), "=r"(r2), "=r"(r3) : "r"(a))
#define LDSM4T(r0, r1, r2, r3, a) \
    asm volatile("ldmatrix.sync.aligned.m8n8.x4.trans.shared.b16 {%0,%1,%2,%3}, [%4];" \
                 : "=r"(r0), "=r"(r1), "=r"(r2), "=r"(r3) : "r"(a))
#define MMAF16(d, a, b0, b1) \
    asm volatile("mma.sync.aligned.m16n8k16.row.col.f32.f16.f16.f32 " \
                 "{%0,%1,%2,%3},{%4,%5,%6,%7},{%8,%9},{%0,%1,%2,%3};" \
                 : "+f"((d)[0]), "+f"((d)[1]), "+f"((d)[2]), "+f"((d)[3]) \
                 : "r"((a)[0]), "r"((a)[1]), "r"((a)[2]), "r"((a)[3]), "r"(b0), "r"(b1))

__global__ __launch_bounds__(128, 2)
void diffunpool_f16_v4(const float* __restrict__ S, float* __restrict__ O) {
    __shared__ __align__(16) char smbuf[SM_BYTES];

    const int nt = blockIdx.x;   // 0..1
    const int mt = blockIdx.y;   // 0..15
    const int b  = blockIdx.z;   // 0..15

    const float*  Sb  = S + ((size_t)b * 2048 + (size_t)mt * 128) * 256;
    const __half* Xb  = g_X16 + (size_t)b * 65536 + (size_t)nt * 128;
    float*        Ob  = O + ((size_t)b * 2048 + (size_t)mt * 128) * 256 + (size_t)nt * 128;

    const int tid = threadIdx.x, wid = tid >> 5, lane = tid & 31;
    const int wm = (wid & 1) * 64;
    const int wn = (wid >> 1) * 64;
    const uint32_t sb = cvta_smem(smbuf);

    // ---- A staging (R12 verbatim)
    const int a_m = tid >> 2, a_seg = tid & 3;
    const float*   pA   = Sb + (size_t)a_m * 256 + a_seg * 8;
    const uint32_t aSts = (uint32_t)a_m * 64 + (uint32_t)((a_seg ^ ((a_m >> 1) & 3)) << 4);

    // ---- B cp.async into 4-buffer ring (layout/swizzle R12 verbatim)
    auto issueB = [&](int c) {
        const uint32_t bbuf = sb + OFF_B + (uint32_t)(c & 3) * B_BUF;
#pragma unroll
        for (int q = 0; q < 4; q++) {
            int flat = q * 128 + tid;
            int k = flat >> 4, s = flat & 15;
            const __half* src = Xb + (size_t)(c * 32 + k) * 256 + s * 8;
            uint32_t dst = bbuf + (uint32_t)k * 256 + (uint32_t)((s ^ (k & 7)) << 4);
            CP16(dst, src);
        }
        CPCOMMIT();
    };

    // ---- fragment addressing (R12 verbatim)
    const int m_low = (lane & 7) + 8 * ((lane >> 3) & 1);
    const int halfk = lane >> 4;
    uint32_t rowA[4], swzA[4];
#pragma unroll
    for (int mf = 0; mf < 4; mf++) {
        int row = wm + mf * 16 + m_low;
        rowA[mf] = (uint32_t)row * 64;
        swzA[mf] = (uint32_t)((row >> 1) & 3);
    }
    const int b_kl  = lane & 15;
    const int kswz  = b_kl & 7;
    const int b_c0  = (wn >> 3) + (lane >> 4);
    const uint32_t bRow = (uint32_t)b_kl * 256;

    float d[4][8][4];
#pragma unroll
    for (int mf = 0; mf < 4; mf++)
#pragma unroll
        for (int j = 0; j < 8; j++)
#pragma unroll
            for (int r = 0; r < 4; r++) d[mf][j][r] = 0.0f;

    // ---- prologue: A chunk 0 in regs; B chunks 0,1,2 in flight
    float4 va[8];
#pragma unroll
    for (int q = 0; q < 4; q++) {
        va[2*q]   = *(const float4*)(pA + (size_t)q * 8192);
        va[2*q+1] = *(const float4*)(pA + (size_t)q * 8192 + 4);
    }
    issueB(0);
    issueB(1);
    issueB(2);

    for (int c = 0; c < 8; c++) {
        const uint32_t aOff = (uint32_t)(c & 1) * A_BUF;
        const uint32_t bOff = (uint32_t)(c & 3) * B_BUF;

        // ---- STS A(c) into buf c&1 (its last readers, compute(c-1), passed
        //      barrier(c-1)... wait: buf c&1 was read by compute(c-2), which
        //      preceded barrier(c-1) in all warps; this STS follows it). safe.
        //      NOTE for c>0 this STS executes after compute(c-1) in program
        //      order; buffer (c&1) last read by compute(c-2) < barrier(c-1).
#pragma unroll
        for (int q = 0; q < 4; q++)
            *(uint4*)(smbuf + aOff + aSts + q * 2048) = cvt8(va[2*q], va[2*q+1]);

        CPWAIT2();                 // exactly groups c+1, c+2 pending -> B(c) done
        __syncthreads();           // the ONLY barrier per chunk

        // ---- prefetch A chunk c+1 (consumed at next STS, after compute(c))
        if (c < 7) {
            const float* nA = pA + (c + 1) * 32;
#pragma unroll
            for (int q = 0; q < 4; q++) {
                va[2*q]   = *(const float4*)(nA + (size_t)q * 8192);
                va[2*q+1] = *(const float4*)(nA + (size_t)q * 8192 + 4);
            }
        }

        // ---- compute chunk c (R12 verbatim)
#pragma unroll
        for (int ks = 0; ks < 2; ks++) {
            uint32_t a[4][4];
#pragma unroll
            for (int mf = 0; mf < 4; mf++) {
                uint32_t seg  = (uint32_t)(2 * ks + halfk);
                uint32_t addr = sb + aOff + rowA[mf] + ((seg ^ swzA[mf]) << 4);
                LDSM4(a[mf][0], a[mf][1], a[mf][2], a[mf][3], addr);
            }
            uint32_t bb[4][4];
            const uint32_t bkoff = sb + OFF_B + bOff + (uint32_t)(ks * 4096) + bRow;
#pragma unroll
            for (int nb = 0; nb < 4; nb++) {
                uint32_t chunk = (uint32_t)((b_c0 + nb * 2) ^ kswz);
                LDSM4T(bb[nb][0], bb[nb][1], bb[nb][2], bb[nb][3], bkoff + (chunk << 4));
            }
#pragma unroll
            for (int mf = 0; mf < 4; mf++)
#pragma unroll
                for (int nb = 0; nb < 4; nb++) {
                    MMAF16(d[mf][2*nb],   a[mf], bb[nb][0], bb[nb][1]);
                    MMAF16(d[mf][2*nb+1], a[mf], bb[nb][2], bb[nb][3]);
                }
        }

        // ---- issue B(c+3) into buf (c+3)&3: its last readers, compute(c-1),
        //      all passed barrier(c). Empty commit keeps group accounting exact
        //      so CPWAIT2 above always means "group c complete".
        if (c < 5) issueB(c + 3);
        else if (c < 7) CPCOMMIT();     // empty group, completes immediately
    }

    // ---- epilogue (R12 verbatim)
    const int group = lane >> 2;
    const int tcol  = (lane & 3) * 2;
#pragma unroll
    for (int mf = 0; mf < 4; mf++) {
        int m0 = wm + mf * 16 + group;
#pragma unroll
        for (int j = 0; j < 8; j++) {
            int n0 = wn + j * 8 + tcol;
            *(float2*)(Ob + (size_t)m0 * 256 + n0)       = make_float2(d[mf][j][0], d[mf][j][1]);
            *(float2*)(Ob + (size_t)(m0 + 8) * 256 + n0) = make_float2(d[mf][j][2], d[mf][j][3]);
        }
    }
}

extern "C" void kernel_launch(void* const* d_in, const int* in_sizes, int n_in,
                              void* d_out, int out_size) {
    const float* S = nullptr;
    const float* X = nullptr;
    for (int i = 0; i < n_in; i++) {
        if (in_sizes[i] == 8388608)      S = (const float*)d_in[i];
        else if (in_sizes[i] == 1048576) X = (const float*)d_in[i];
    }
    float* O = (float*)d_out;

    convert_x<<<512, 256>>>(X);
    dim3 grid(2, 16, 16);
    diffunpool_f16_v4<<<grid, 128>>>(S, O);
}